// round 8
// baseline (speedup 1.0000x reference)
#include <cuda_runtime.h>
#include <math.h>

#define D 128
#define SEGS 32
#define SROWS 64            // rows per seg-sum tile
#define GROWS 64            // rows per gate tile
#define MAXBPS 6            // blocks per SM cap (256 thr -> 1536 thr/SM)

// Scratch — zero-initialized at module load; kernel self-restores all mutable
// state at the end of every launch (capture/replay safe).
__device__ __align__(16) float g_sums[SEGS * D];
__device__ float g_cnt[SEGS];
__device__ __align__(16) float g_gateV[SEGS * D];
__device__ __align__(16) float g_gateE[SEGS * D];
__device__ unsigned int g_done = 0;   // blocks finished seg phase
__device__ unsigned int g_mlp  = 0;   // segments with gates ready
__device__ unsigned int g_fin  = 0;   // blocks finished gate phase

// ---------------------------------------------------------------------------
__device__ __forceinline__ void prefetch_l2(const void* p, int bytes, int t) {
    for (int off = t * 128; off < bytes; off += 256 * 128)
        asm volatile("prefetch.global.L2 [%0];" :: "l"((const char*)p + off));
}

// 256-thread MLP layer: output's 128-dot split in 2 halves (64 FMAs each).
__device__ __forceinline__ void mlp_layer256(
    const float* __restrict__ sin, float* __restrict__ sout,
    const float* __restrict__ W, const float* __restrict__ b,
    float* __restrict__ sred, int t128, int part, bool do_relu) {
    float p = 0.0f;
    const float* Wp = W + (part * 64) * D + t128;
    const float* xp = sin + part * 64;
#pragma unroll
    for (int k = 0; k < 64; k++)
        p = fmaf(xp[k], __ldg(&Wp[k * D]), p);
    sred[part * D + t128] = p;
    __syncthreads();
    if (part == 0) {
        float v = sred[t128] + sred[D + t128] + __ldg(&b[t128]);
        sout[t128] = do_relu ? fmaxf(v, 0.0f) : v;
    }
    __syncthreads();
}

// ---------------------------------------------------------------------------
// One persistent launch: seg sums -> (MLP || gate-tile L2 prefetch) -> gating.
// Grid = exactly one co-resident wave (host queries occupancy), so the
// counter-based phase barriers cannot deadlock.
__global__ void __launch_bounds__(256, MAXBPS) persist_kernel(
    const float* __restrict__ x, const float* __restrict__ ea,
    const int* __restrict__ eidx, const int* __restrict__ bid,
    float* __restrict__ outN, float* __restrict__ outE, int N, int E,
    const float* __restrict__ VW1, const float* __restrict__ Vb1,
    const float* __restrict__ VW2, const float* __restrict__ Vb2,
    const float* __restrict__ VW3, const float* __restrict__ Vb3,
    const float* __restrict__ EW1, const float* __restrict__ Eb1,
    const float* __restrict__ EW2, const float* __restrict__ Eb2,
    const float* __restrict__ EW3, const float* __restrict__ Eb3) {
    __shared__ float pool[8 * D];            // 4 KB, re-used across phases
    int t = threadIdx.x;
    int b = blockIdx.x;
    int G = gridDim.x;

    // MLP blocks kick weight prefetch immediately (overlaps with seg phase).
    if (b < SEGS) {
        prefetch_l2(VW1, D * D * 4, t); prefetch_l2(VW2, D * D * 4, t);
        prefetch_l2(VW3, D * D * 4, t); prefetch_l2(EW1, D * D * 4, t);
        prefetch_l2(EW2, D * D * 4, t); prefetch_l2(EW3, D * D * 4, t);
    }

    // ---------------- phase 1: segment sums ----------------
    int sumTiles = (N + SROWS - 1) / SROWS;
    for (int tile = b; tile < sumTiles; tile += G) {
        int r0 = tile * SROWS;
        int rlast = min(r0 + SROWS, N) - 1;
        int s0 = __ldg(&bid[r0]);
        int s1 = __ldg(&bid[rlast]);

        if (s0 == s1) {
            float (*sred)[D] = (float(*)[D])pool;
            int f4c = t & 31;        // float4 column
            int rg  = t >> 5;        // row group 0..7
            const float4* xf4 = (const float4*)x;
            size_t base = (size_t)(r0 + rg) * 32 + f4c;
            float4 acc = make_float4(0.f, 0.f, 0.f, 0.f);
            if (r0 + SROWS <= N) {
                float4 a[8];
#pragma unroll
                for (int j = 0; j < 8; j++)
                    a[j] = xf4[base + (size_t)j * 8 * 32];
#pragma unroll
                for (int j = 0; j < 8; j++) {
                    acc.x += a[j].x; acc.y += a[j].y;
                    acc.z += a[j].z; acc.w += a[j].w;
                }
            } else {
#pragma unroll
                for (int j = 0; j < 8; j++) {
                    if (r0 + rg + j * 8 < N) {
                        float4 v = xf4[base + (size_t)j * 8 * 32];
                        acc.x += v.x; acc.y += v.y; acc.z += v.z; acc.w += v.w;
                    }
                }
            }
            *(float4*)&sred[rg][f4c * 4] = acc;
            __syncthreads();
            if (t < D) {
                float s = (sred[0][t] + sred[1][t]) + (sred[2][t] + sred[3][t])
                        + (sred[4][t] + sred[5][t]) + (sred[6][t] + sred[7][t]);
                atomicAdd(&g_sums[s0 * D + t], s);
                if (t == 0) atomicAdd(&g_cnt[s0], (float)(rlast - r0 + 1));
            }
        } else {
            // segment boundary inside tile (rare): scalar walk on 128 thr
            if (t < D) {
                float acc = 0.0f, cnt = 0.0f;
                int cur = s0;
                for (int r = r0; r <= rlast; r++) {
                    int s = __ldg(&bid[r]);
                    if (s != cur) {
                        atomicAdd(&g_sums[cur * D + t], acc);
                        if (t == 0) atomicAdd(&g_cnt[cur], cnt);
                        acc = 0.0f; cnt = 0.0f; cur = s;
                    }
                    acc += x[(size_t)r * D + t];
                    cnt += 1.0f;
                }
                atomicAdd(&g_sums[cur * D + t], acc);
                if (t == 0) atomicAdd(&g_cnt[cur], cnt);
            }
        }
        __syncthreads();   // pool reuse barrier before next tile
    }
    if (t == 0) {
        __threadfence();                    // release seg atomics
        atomicAdd(&g_done, 1u);
    }

    int nodeTiles = (N + GROWS - 1) / GROWS;
    int edgeTiles = (E + GROWS - 1) / GROWS;
    int T = nodeTiles + edgeTiles;

    // ---------------- phase 2: MLP (blocks 0..31) ----------------
    if (b < SEGS) {
        int seg = b;
        if (t == 0) {
            while (atomicAdd(&g_done, 0u) < (unsigned)G) __nanosleep(32);
            __threadfence();                // acquire
        }
        __syncthreads();

        float* scv  = pool;
        float* bufA = pool + D;
        float* bufB = pool + 2 * D;
        float* sred = pool + 3 * D;         // 2*D
        int t128 = t & 127;
        int part = t >> 7;

        if (t < D) {
            float cnt = fmaxf(g_cnt[seg], 1.0f);
            scv[t] = g_sums[seg * D + t] / cnt;
        }
        __syncthreads();

        // V MLP
        mlp_layer256(scv,  bufA, VW1, Vb1, sred, t128, part, true);
        mlp_layer256(bufA, bufB, VW2, Vb2, sred, t128, part, true);
        mlp_layer256(bufB, bufA, VW3, Vb3, sred, t128, part, false);
        if (t < D) {
            float gV = 1.0f / (1.0f + expf(-bufA[t]));
            g_gateV[seg * D + t] = gV;
            bufB[t] = scv[t] * gV;          // c_V2 = c_V * gate_V (exact)
        }
        __syncthreads();

        // E MLP
        mlp_layer256(bufB, bufA, EW1, Eb1, sred, t128, part, true);
        mlp_layer256(bufA, bufB, EW2, Eb2, sred, t128, part, true);
        mlp_layer256(bufB, bufA, EW3, Eb3, sred, t128, part, false);
        if (t < D) {
            g_gateE[seg * D + t] = 1.0f / (1.0f + expf(-bufA[t]));
            // restore scratch (zero-invariant at launch entry)
            g_sums[seg * D + t] = 0.0f;
            if (t == 0) g_cnt[seg] = 0.0f;
        }
        __syncthreads();
        if (t == 0) {
            __threadfence();
            atomicAdd(&g_mlp, 1u);
        }
    } else {
        // Non-MLP blocks: L2-prefetch first gate tiles while MLP runs.
        for (int k = 0; k < 2; k++) {
            int tile = b + k * G;
            if (tile < nodeTiles) {
                prefetch_l2((const char*)x + (size_t)tile * GROWS * D * 4,
                            GROWS * D * 4, t);
            } else if (tile < T) {
                prefetch_l2((const char*)ea +
                            (size_t)(tile - nodeTiles) * GROWS * D * 4,
                            GROWS * D * 4, t);
            }
        }
    }

    // all blocks wait until every gate row is ready
    if (t == 0) {
        while (atomicAdd(&g_mlp, 0u) < SEGS) __nanosleep(32);
        __threadfence();                    // acquire
    }
    __syncthreads();

    // ---------------- phase 3: gating ----------------
    for (int tile = b; tile < T; tile += G) {
        if (tile < nodeTiles) {
            int r0 = tile * GROWS;
            const float4* src = (const float4*)x;
            float4* dst = (float4*)outN;
            long long base = (long long)r0 * 32;
#pragma unroll
            for (int it = 0; it < 8; it++) {
                int i = it * 256 + t;
                int r = r0 + (i >> 5);              // warp-uniform
                if (r < N) {
                    int s = __ldg(&bid[r]);         // broadcast
                    float4 g = *(const float4*)&g_gateV[s * D + (i & 31) * 4];
                    float4 v = src[base + i];
                    v.x *= g.x; v.y *= g.y; v.z *= g.z; v.w *= g.w;
                    __stcs(&dst[base + i], v);
                }
            }
        } else {
            int r0 = (tile - nodeTiles) * GROWS;
            const float4* src = (const float4*)ea;
            float4* dst = (float4*)outE;
            long long base = (long long)r0 * 32;
#pragma unroll
            for (int it = 0; it < 8; it++) {
                int i = it * 256 + t;
                int r = r0 + (i >> 5);              // warp-uniform
                if (r < E) {
                    int s = __ldg(&bid[__ldg(&eidx[r])]);   // 2 broadcasts
                    float4 g = *(const float4*)&g_gateE[s * D + (i & 31) * 4];
                    float4 v = __ldcs(&src[base + i]);
                    v.x *= g.x; v.y *= g.y; v.z *= g.z; v.w *= g.w;
                    __stcs(&dst[base + i], v);
                }
            }
        }
    }

    // ---------------- epilogue: reset counters for replay ----------------
    __syncthreads();
    if (t == 0) {
        __threadfence();
        unsigned o = atomicAdd(&g_fin, 1u);
        if (o == (unsigned)G - 1) {         // last block: exclusive access
            g_done = 0u;
            g_mlp  = 0u;
            g_fin  = 0u;
        }
    }
}

// ---------------------------------------------------------------------------
extern "C" void kernel_launch(void* const* d_in, const int* in_sizes, int n_in,
                              void* d_out, int out_size) {
    const float* dst_na  = (const float*)d_in[0];
    const float* ea      = (const float*)d_in[1];
    const int*   eidx    = (const int*)d_in[2];   // [2, E], row 0 = src
    const int*   bid     = (const int*)d_in[3];
    const float* VW1 = (const float*)d_in[4];
    const float* Vb1 = (const float*)d_in[5];
    const float* VW2 = (const float*)d_in[6];
    const float* Vb2 = (const float*)d_in[7];
    const float* VW3 = (const float*)d_in[8];
    const float* Vb3 = (const float*)d_in[9];
    const float* EW1 = (const float*)d_in[10];
    const float* Eb1 = (const float*)d_in[11];
    const float* EW2 = (const float*)d_in[12];
    const float* Eb2 = (const float*)d_in[13];
    const float* EW3 = (const float*)d_in[14];
    const float* Eb3 = (const float*)d_in[15];

    int N = in_sizes[0] / D;
    int E = in_sizes[1] / D;
    float* out_nodes = (float*)d_out;
    float* out_edges = (float*)d_out + (size_t)N * D;

    // Grid = exactly one co-resident wave (deadlock-free phase barriers).
    static int gridBlocks = 0;
    if (gridBlocks == 0) {
        int dev = 0, numSM = 148, bps = 0;
        cudaGetDevice(&dev);
        cudaDeviceGetAttribute(&numSM, cudaDevAttrMultiProcessorCount, dev);
        cudaOccupancyMaxActiveBlocksPerMultiprocessor(
            &bps, persist_kernel, 256, 0);
        if (bps < 1) bps = 1;
        if (bps > MAXBPS) bps = MAXBPS;
        gridBlocks = numSM * bps;
        if (gridBlocks < SEGS + 1) gridBlocks = SEGS + 1;
    }

    persist_kernel<<<gridBlocks, 256>>>(
        dst_na, ea, eidx, bid, out_nodes, out_edges, N, E,
        VW1, Vb1, VW2, Vb2, VW3, Vb3,
        EW1, Eb1, EW2, Eb2, EW3, Eb3);
}

// round 9
// speedup vs baseline: 1.1486x; 1.1486x over previous
#include <cuda_runtime.h>
#include <math.h>

#define D 128
#define SEGS 32
#define SROWS 128           // rows per seg_sum block
#define GROWS 64            // rows per gate block

// Scratch — zero-initialized at module load; mlp_kernel re-zeroes at its end
// so every launch (correctness, capture, replay) starts clean.
__device__ __align__(16) float g_sums[SEGS * D];
__device__ float g_cnt[SEGS];
__device__ __align__(16) float g_gateV[SEGS * D];
__device__ __align__(16) float g_gateE[SEGS * D];

// ---------------------------------------------------------------------------
__device__ __forceinline__ void prefetch_l2(const void* p, int bytes, int t) {
    for (int off = t * 128; off < bytes; off += 256 * 128)
        asm volatile("prefetch.global.L2 [%0];" :: "l"((const char*)p + off));
}

// ---------------------------------------------------------------------------
// Segment sums over sorted batch_id. 256 threads per 128 rows -> 782 blocks.
// Each thread: 2 batches of 8 independent float4 loads (no barrier between
// batches -> sustained MLP~8), one smem reduce + 128 atomics per block.
// Blocks [sumBlocks, sumBlocks+8) only prefetch MLP weights into L2 and exit
// (warms the next kernel for free).
__global__ void __launch_bounds__(256) seg_sum_kernel(
    const float* __restrict__ x, const int* __restrict__ bid, int N,
    int sumBlocks,
    const float* __restrict__ VW1, const float* __restrict__ VW2,
    const float* __restrict__ VW3, const float* __restrict__ EW1,
    const float* __restrict__ EW2, const float* __restrict__ EW3) {
    int b = blockIdx.x;
    int t = threadIdx.x;

    if (b >= sumBlocks) {
        // weight prefetch role (8 blocks, one matrix-half each)
        int role = b - sumBlocks;
        const float* Ws[6] = {VW1, VW2, VW3, EW1, EW2, EW3};
        if (role < 6) prefetch_l2(Ws[role], D * D * 4, t);
        return;
    }

    int r0 = b * SROWS;
    int rlast = min(r0 + SROWS, N) - 1;
    int s0 = __ldg(&bid[r0]);
    int s1 = __ldg(&bid[rlast]);

    if (s0 == s1) {
        __shared__ float sred[8][D];
        int f4c = t & 31;            // float4 column 0..31
        int rg  = t >> 5;            // row group 0..7
        const float4* xf4 = (const float4*)x;   // 32 float4 per row
        size_t base = (size_t)(r0 + rg) * 32 + f4c;

        float4 acc = make_float4(0.f, 0.f, 0.f, 0.f);
        if (r0 + SROWS <= N) {       // full block: unguarded, batched
#pragma unroll
            for (int half = 0; half < 2; half++) {
                float4 a[8];
#pragma unroll
                for (int j = 0; j < 8; j++)
                    a[j] = xf4[base + (size_t)(half * 64 + j * 8) * 32];
#pragma unroll
                for (int j = 0; j < 8; j++) {
                    acc.x += a[j].x; acc.y += a[j].y;
                    acc.z += a[j].z; acc.w += a[j].w;
                }
            }
        } else {
#pragma unroll
            for (int j = 0; j < 16; j++) {
                if (r0 + rg + j * 8 < N) {
                    float4 v = xf4[base + (size_t)(j * 8) * 32];
                    acc.x += v.x; acc.y += v.y; acc.z += v.z; acc.w += v.w;
                }
            }
        }
        *(float4*)&sred[rg][f4c * 4] = acc;
        __syncthreads();
        if (t < D) {
            float s = (sred[0][t] + sred[1][t]) + (sred[2][t] + sred[3][t])
                    + (sred[4][t] + sred[5][t]) + (sred[6][t] + sred[7][t]);
            atomicAdd(&g_sums[s0 * D + t], s);
            if (t == 0) atomicAdd(&g_cnt[s0], (float)(rlast - r0 + 1));
        }
    } else {
        // slow path: segment boundary inside block (~31 of 782 blocks);
        // lower 128 threads scalar-walk with boundary flushes.
        if (t < D) {
            float acc = 0.0f, cnt = 0.0f;
            int cur = s0;
            for (int r = r0; r <= rlast; r++) {
                int s = __ldg(&bid[r]);
                if (s != cur) {
                    atomicAdd(&g_sums[cur * D + t], acc);
                    if (t == 0) atomicAdd(&g_cnt[cur], cnt);
                    acc = 0.0f; cnt = 0.0f; cur = s;
                }
                acc += x[(size_t)r * D + t];
                cnt += 1.0f;
            }
            atomicAdd(&g_sums[cur * D + t], acc);
            if (t == 0) atomicAdd(&g_cnt[cur], cnt);
        }
    }
}

// ---------------------------------------------------------------------------
// MLPs: 32 blocks (one per segment) x 512 threads, weights L2-warm from the
// seg_sum prefetch blocks. Each output's 128-dot split 4 ways, smem reduce.
// gate_V = sig(mlpV(c_V)); c_V2 = c_V*gate_V (exact: gate const per segment,
// mean linear); gate_E = sig(mlpE(c_V2)). Re-zeroes scratch at the end.
__device__ __forceinline__ void mlp_layer(
    const float* __restrict__ sin, float* __restrict__ sout,
    const float* __restrict__ W, const float* __restrict__ b,
    float (*sred)[D], int t128, int part, bool do_relu) {
    float p = 0.0f;
    const float* Wp = W + (part * 32) * D + t128;
    const float* xp = sin + part * 32;
#pragma unroll
    for (int k = 0; k < 32; k++)
        p = fmaf(xp[k], __ldg(&Wp[k * D]), p);
    sred[part][t128] = p;
    __syncthreads();
    if (part == 0) {
        float v = sred[0][t128] + sred[1][t128] + sred[2][t128] + sred[3][t128]
                + __ldg(&b[t128]);
        sout[t128] = do_relu ? fmaxf(v, 0.0f) : v;
    }
    __syncthreads();
}

__global__ void __launch_bounds__(512) mlp_kernel(
    const float* __restrict__ VW1, const float* __restrict__ Vb1,
    const float* __restrict__ VW2, const float* __restrict__ Vb2,
    const float* __restrict__ VW3, const float* __restrict__ Vb3,
    const float* __restrict__ EW1, const float* __restrict__ Eb1,
    const float* __restrict__ EW2, const float* __restrict__ Eb2,
    const float* __restrict__ EW3, const float* __restrict__ Eb3) {
    __shared__ float scv[D], bufA[D], bufB[D];
    __shared__ float sred[4][D];
    int seg = blockIdx.x;
    int t = threadIdx.x;
    int t128 = t & 127;
    int part = t >> 7;

    if (t < D) {
        float cnt = fmaxf(g_cnt[seg], 1.0f);
        scv[t] = g_sums[seg * D + t] / cnt;
    }
    __syncthreads();

    // --- V MLP ---
    mlp_layer(scv,  bufA, VW1, Vb1, sred, t128, part, true);
    mlp_layer(bufA, bufB, VW2, Vb2, sred, t128, part, true);
    mlp_layer(bufB, bufA, VW3, Vb3, sred, t128, part, false);
    if (t < D) {
        float gV = 1.0f / (1.0f + expf(-bufA[t]));
        g_gateV[seg * D + t] = gV;
        bufB[t] = scv[t] * gV;     // c_V2
    }
    __syncthreads();

    // --- E MLP ---
    mlp_layer(bufB, bufA, EW1, Eb1, sred, t128, part, true);
    mlp_layer(bufA, bufB, EW2, Eb2, sred, t128, part, true);
    mlp_layer(bufB, bufA, EW3, Eb3, sred, t128, part, false);
    if (t < D) {
        g_gateE[seg * D + t] = 1.0f / (1.0f + expf(-bufA[t]));
        // restore scratch for the next launch (zero-invariant at entry)
        g_sums[seg * D + t] = 0.0f;
        if (t == 0) g_cnt[seg] = 0.0f;
    }
}

// ---------------------------------------------------------------------------
// Gating. Blocks [0, nodeBlocks) gate nodes; rest gate edges. 64 rows/block,
// 8 float4 iterations; row index is warp-uniform so bid/eidx loads are
// broadcasts — no smem, no barrier. Edges stream with __ldcs/__stcs.
__global__ void __launch_bounds__(256) gate_kernel(
    const float* __restrict__ x, const float* __restrict__ ea,
    const int* __restrict__ eidx, const int* __restrict__ bid,
    float* __restrict__ outN, float* __restrict__ outE,
    int N, int E, int nodeBlocks) {
    int t = threadIdx.x;
    int b = blockIdx.x;

    if (b < nodeBlocks) {
        int r0 = b * GROWS;
        const float4* src = (const float4*)x;
        float4* dst = (float4*)outN;
        long long base = (long long)r0 * 32;
#pragma unroll
        for (int it = 0; it < 8; it++) {
            int i = it * 256 + t;
            int r = r0 + (i >> 5);             // warp-uniform
            if (r < N) {
                int s = __ldg(&bid[r]);        // broadcast
                float4 g = *(const float4*)&g_gateV[s * D + (i & 31) * 4];
                float4 v = src[base + i];
                v.x *= g.x; v.y *= g.y; v.z *= g.z; v.w *= g.w;
                __stcs(&dst[base + i], v);
            }
        }
    } else {
        int r0 = (b - nodeBlocks) * GROWS;
        const float4* src = (const float4*)ea;
        float4* dst = (float4*)outE;
        long long base = (long long)r0 * 32;
#pragma unroll
        for (int it = 0; it < 8; it++) {
            int i = it * 256 + t;
            int r = r0 + (i >> 5);             // warp-uniform
            if (r < E) {
                int s = __ldg(&bid[__ldg(&eidx[r])]);   // 2 broadcasts
                float4 g = *(const float4*)&g_gateE[s * D + (i & 31) * 4];
                float4 v = __ldcs(&src[base + i]);
                v.x *= g.x; v.y *= g.y; v.z *= g.z; v.w *= g.w;
                __stcs(&dst[base + i], v);
            }
        }
    }
}

// ---------------------------------------------------------------------------
extern "C" void kernel_launch(void* const* d_in, const int* in_sizes, int n_in,
                              void* d_out, int out_size) {
    const float* dst_na  = (const float*)d_in[0];
    const float* ea      = (const float*)d_in[1];
    const int*   eidx    = (const int*)d_in[2];   // [2, E], row 0 = src
    const int*   bid     = (const int*)d_in[3];
    const float* VW1 = (const float*)d_in[4];
    const float* Vb1 = (const float*)d_in[5];
    const float* VW2 = (const float*)d_in[6];
    const float* Vb2 = (const float*)d_in[7];
    const float* VW3 = (const float*)d_in[8];
    const float* Vb3 = (const float*)d_in[9];
    const float* EW1 = (const float*)d_in[10];
    const float* Eb1 = (const float*)d_in[11];
    const float* EW2 = (const float*)d_in[12];
    const float* Eb2 = (const float*)d_in[13];
    const float* EW3 = (const float*)d_in[14];
    const float* Eb3 = (const float*)d_in[15];

    int N = in_sizes[0] / D;
    int E = in_sizes[1] / D;
    float* out_nodes = (float*)d_out;
    float* out_edges = (float*)d_out + (size_t)N * D;

    int sumBlocks = (N + SROWS - 1) / SROWS;
    seg_sum_kernel<<<sumBlocks + 8, 256>>>(dst_na, bid, N, sumBlocks,
                                           VW1, VW2, VW3, EW1, EW2, EW3);

    mlp_kernel<<<SEGS, 512>>>(VW1, Vb1, VW2, Vb2, VW3, Vb3,
                              EW1, Eb1, EW2, Eb2, EW3, Eb3);

    int nodeBlocks = (N + GROWS - 1) / GROWS;
    int edgeBlocks = (E + GROWS - 1) / GROWS;
    gate_kernel<<<nodeBlocks + edgeBlocks, 256>>>(
        dst_na, ea, eidx, bid, out_nodes, out_edges, N, E, nodeBlocks);
}

// round 11
// speedup vs baseline: 1.3277x; 1.1559x over previous
#include <cuda_runtime.h>
#include <math.h>

#define D 128
#define SEGS 32
#define SROWS 32            // rows per seg_sum block (3125 blocks — proven best)
#define GROWS 64            // rows per gate block

// Scratch — zero-initialized at module load; mlp_kernel re-zeroes at its end
// so every launch (correctness, capture, replay) starts clean.
__device__ __align__(16) float g_sums[SEGS * D];
__device__ float g_cnt[SEGS];
__device__ __align__(16) float g_gateV[SEGS * D];
__device__ __align__(16) float g_gateE[SEGS * D];

// ---------------------------------------------------------------------------
__device__ __forceinline__ void prefetch_l2(const void* p, int bytes, int t) {
    for (int off = t * 128; off < bytes; off += 256 * 128)
        asm volatile("prefetch.global.L2 [%0];" :: "l"((const char*)p + off));
}

// ---------------------------------------------------------------------------
// Segment sums over sorted batch_id. 256 threads per 32 rows -> 3125 blocks
// (dense waves — block count, not per-thread batching, is what feeds the
// memory system; measured 21.9us in this exact config). Each thread: 4
// independent front-batched float4 loads, smem reduce, 128 atomics/block.
// 6 extra tail blocks prefetch MLP weights into L2 (measured: cuts the
// mlp kernel's cold-weight cost from ~25us to ~4us).
__global__ void __launch_bounds__(256) seg_sum_kernel(
    const float* __restrict__ x, const int* __restrict__ bid, int N,
    int sumBlocks,
    const float* __restrict__ VW1, const float* __restrict__ VW2,
    const float* __restrict__ VW3, const float* __restrict__ EW1,
    const float* __restrict__ EW2, const float* __restrict__ EW3) {
    int b = blockIdx.x;
    int t = threadIdx.x;

    if (b >= sumBlocks) {
        // weight-prefetch role (6 blocks, one matrix each)
        int role = b - sumBlocks;
        const float* Ws[6] = {VW1, VW2, VW3, EW1, EW2, EW3};
        if (role < 6) prefetch_l2(Ws[role], D * D * 4, t);
        return;
    }

    int r0 = b * SROWS;
    if (r0 >= N) return;
    int rlast = min(r0 + SROWS, N) - 1;

    int s0 = __ldg(&bid[r0]);
    int s1 = __ldg(&bid[rlast]);

    if (s0 == s1) {
        __shared__ float sred[8][D];
        int f4c = t & 31;            // float4 column 0..31
        int rg  = t >> 5;            // row group 0..7
        const float4* xf4 = (const float4*)x;   // 32 float4 per row
        size_t base = (size_t)(r0 + rg) * 32 + f4c;

        float4 a0, a1, a2, a3;
        if (r0 + SROWS <= N) {       // full block: unguarded, batched
            a0 = xf4[base];
            a1 = xf4[base + 8 * 32];
            a2 = xf4[base + 16 * 32];
            a3 = xf4[base + 24 * 32];
        } else {
            float4 z = make_float4(0.f, 0.f, 0.f, 0.f);
            a0 = (r0 + rg      < N) ? xf4[base]           : z;
            a1 = (r0 + rg + 8  < N) ? xf4[base + 8 * 32]  : z;
            a2 = (r0 + rg + 16 < N) ? xf4[base + 16 * 32] : z;
            a3 = (r0 + rg + 24 < N) ? xf4[base + 24 * 32] : z;
        }
        float4 acc;
        acc.x = (a0.x + a1.x) + (a2.x + a3.x);
        acc.y = (a0.y + a1.y) + (a2.y + a3.y);
        acc.z = (a0.z + a1.z) + (a2.z + a3.z);
        acc.w = (a0.w + a1.w) + (a2.w + a3.w);
        *(float4*)&sred[rg][f4c * 4] = acc;
        __syncthreads();
        if (t < D) {
            float s = (sred[0][t] + sred[1][t]) + (sred[2][t] + sred[3][t])
                    + (sred[4][t] + sred[5][t]) + (sred[6][t] + sred[7][t]);
            atomicAdd(&g_sums[s0 * D + t], s);
            if (t == 0) atomicAdd(&g_cnt[s0], (float)(rlast - r0 + 1));
        }
    } else {
        // slow path: segment boundary inside block (~1% of blocks);
        // lower 128 threads scalar-walk with boundary flushes.
        if (t < D) {
            float acc = 0.0f, cnt = 0.0f;
            int cur = s0;
            for (int r = r0; r <= rlast; r++) {
                int s = __ldg(&bid[r]);
                if (s != cur) {
                    atomicAdd(&g_sums[cur * D + t], acc);
                    if (t == 0) atomicAdd(&g_cnt[cur], cnt);
                    acc = 0.0f; cnt = 0.0f; cur = s;
                }
                acc += x[(size_t)r * D + t];
                cnt += 1.0f;
            }
            atomicAdd(&g_sums[cur * D + t], acc);
            if (t == 0) atomicAdd(&g_cnt[cur], cnt);
        }
    }
}

// ---------------------------------------------------------------------------
// MLPs: 32 blocks (one per segment) x 512 threads, weights L2-warm from the
// seg_sum prefetch blocks. Each output's 128-dot split 4 ways, smem reduce.
// gate_V = sig(mlpV(c_V)); c_V2 = c_V*gate_V (exact: gate const per segment,
// mean linear); gate_E = sig(mlpE(c_V2)). Re-zeroes scratch at the end.
__device__ __forceinline__ void mlp_layer(
    const float* __restrict__ sin, float* __restrict__ sout,
    const float* __restrict__ W, const float* __restrict__ b,
    float (*sred)[D], int t128, int part, bool do_relu) {
    float p = 0.0f;
    const float* Wp = W + (part * 32) * D + t128;
    const float* xp = sin + part * 32;
#pragma unroll
    for (int k = 0; k < 32; k++)
        p = fmaf(xp[k], __ldg(&Wp[k * D]), p);
    sred[part][t128] = p;
    __syncthreads();
    if (part == 0) {
        float v = sred[0][t128] + sred[1][t128] + sred[2][t128] + sred[3][t128]
                + __ldg(&b[t128]);
        sout[t128] = do_relu ? fmaxf(v, 0.0f) : v;
    }
    __syncthreads();
}

__global__ void __launch_bounds__(512) mlp_kernel(
    const float* __restrict__ VW1, const float* __restrict__ Vb1,
    const float* __restrict__ VW2, const float* __restrict__ Vb2,
    const float* __restrict__ VW3, const float* __restrict__ Vb3,
    const float* __restrict__ EW1, const float* __restrict__ Eb1,
    const float* __restrict__ EW2, const float* __restrict__ Eb2,
    const float* __restrict__ EW3, const float* __restrict__ Eb3) {
    __shared__ float scv[D], bufA[D], bufB[D];
    __shared__ float sred[4][D];
    int seg = blockIdx.x;
    int t = threadIdx.x;
    int t128 = t & 127;
    int part = t >> 7;

    if (t < D) {
        float cnt = fmaxf(g_cnt[seg], 1.0f);
        scv[t] = g_sums[seg * D + t] / cnt;
    }
    __syncthreads();

    // --- V MLP ---
    mlp_layer(scv,  bufA, VW1, Vb1, sred, t128, part, true);
    mlp_layer(bufA, bufB, VW2, Vb2, sred, t128, part, true);
    mlp_layer(bufB, bufA, VW3, Vb3, sred, t128, part, false);
    if (t < D) {
        float gV = 1.0f / (1.0f + expf(-bufA[t]));
        g_gateV[seg * D + t] = gV;
        bufB[t] = scv[t] * gV;     // c_V2
    }
    __syncthreads();

    // --- E MLP ---
    mlp_layer(bufB, bufA, EW1, Eb1, sred, t128, part, true);
    mlp_layer(bufA, bufB, EW2, Eb2, sred, t128, part, true);
    mlp_layer(bufB, bufA, EW3, Eb3, sred, t128, part, false);
    if (t < D) {
        g_gateE[seg * D + t] = 1.0f / (1.0f + expf(-bufA[t]));
        // restore scratch for the next launch (zero-invariant at entry)
        g_sums[seg * D + t] = 0.0f;
        if (t == 0) g_cnt[seg] = 0.0f;
    }
}

// ---------------------------------------------------------------------------
// Gating. Blocks [0, nodeBlocks) gate nodes; rest gate edges. 64 rows/block,
// 8 float4 iterations; row index is warp-uniform so bid/eidx loads are
// broadcasts — no smem, no barrier. Edges stream with __ldcs/__stcs.
__global__ void __launch_bounds__(256) gate_kernel(
    const float* __restrict__ x, const float* __restrict__ ea,
    const int* __restrict__ eidx, const int* __restrict__ bid,
    float* __restrict__ outN, float* __restrict__ outE,
    int N, int E, int nodeBlocks) {
    int t = threadIdx.x;
    int b = blockIdx.x;

    if (b < nodeBlocks) {
        int r0 = b * GROWS;
        const float4* src = (const float4*)x;
        float4* dst = (float4*)outN;
        long long base = (long long)r0 * 32;
#pragma unroll
        for (int it = 0; it < 8; it++) {
            int i = it * 256 + t;
            int r = r0 + (i >> 5);             // warp-uniform
            if (r < N) {
                int s = __ldg(&bid[r]);        // broadcast
                float4 g = *(const float4*)&g_gateV[s * D + (i & 31) * 4];
                float4 v = src[base + i];
                v.x *= g.x; v.y *= g.y; v.z *= g.z; v.w *= g.w;
                __stcs(&dst[base + i], v);
            }
        }
    } else {
        int r0 = (b - nodeBlocks) * GROWS;
        const float4* src = (const float4*)ea;
        float4* dst = (float4*)outE;
        long long base = (long long)r0 * 32;
#pragma unroll
        for (int it = 0; it < 8; it++) {
            int i = it * 256 + t;
            int r = r0 + (i >> 5);             // warp-uniform
            if (r < E) {
                int s = __ldg(&bid[__ldg(&eidx[r])]);   // 2 broadcasts
                float4 g = *(const float4*)&g_gateE[s * D + (i & 31) * 4];
                float4 v = __ldcs(&src[base + i]);
                v.x *= g.x; v.y *= g.y; v.z *= g.z; v.w *= g.w;
                __stcs(&dst[base + i], v);
            }
        }
    }
}

// ---------------------------------------------------------------------------
extern "C" void kernel_launch(void* const* d_in, const int* in_sizes, int n_in,
                              void* d_out, int out_size) {
    const float* dst_na  = (const float*)d_in[0];
    const float* ea      = (const float*)d_in[1];
    const int*   eidx    = (const int*)d_in[2];   // [2, E], row 0 = src
    const int*   bid     = (const int*)d_in[3];
    const float* VW1 = (const float*)d_in[4];
    const float* Vb1 = (const float*)d_in[5];
    const float* VW2 = (const float*)d_in[6];
    const float* Vb2 = (const float*)d_in[7];
    const float* VW3 = (const float*)d_in[8];
    const float* Vb3 = (const float*)d_in[9];
    const float* EW1 = (const float*)d_in[10];
    const float* Eb1 = (const float*)d_in[11];
    const float* EW2 = (const float*)d_in[12];
    const float* Eb2 = (const float*)d_in[13];
    const float* EW3 = (const float*)d_in[14];
    const float* Eb3 = (const float*)d_in[15];

    int N = in_sizes[0] / D;
    int E = in_sizes[1] / D;
    float* out_nodes = (float*)d_out;
    float* out_edges = (float*)d_out + (size_t)N * D;

    int sumBlocks = (N + SROWS - 1) / SROWS;
    seg_sum_kernel<<<sumBlocks + 6, 256>>>(dst_na, bid, N, sumBlocks,
                                           VW1, VW2, VW3, EW1, EW2, EW3);

    mlp_kernel<<<SEGS, 512>>>(VW1, Vb1, VW2, Vb2, VW3, Vb3,
                              EW1, Eb1, EW2, Eb2, EW3, Eb3);

    int nodeBlocks = (N + GROWS - 1) / GROWS;
    int edgeBlocks = (E + GROWS - 1) / GROWS;
    gate_kernel<<<nodeBlocks + edgeBlocks, 256>>>(
        dst_na, ea, eidx, bid, out_nodes, out_edges, N, E, nodeBlocks);
}